// round 6
// baseline (speedup 1.0000x reference)
#include <cuda_runtime.h>
#include <cuda_fp16.h>

#define NN 50000
#define NE 1600000
#define NG 64
#define NSB ((NN + 255) / 256)   // 196 scan blocks

// ---------------- scratch (static device globals; no allocation) ----------------
__device__ __align__(16) __half g_xl1h[NN * 64];
__device__ __align__(16) __half g_xl2h[NN * 128];
__device__ float g_as1[NN * 2];
__device__ float g_ad1[NN * 2];
__device__ float g_h1[NN * 64];
__device__ float g_as2[NN];
__device__ float g_ad2[NN];
__device__ int   g_deg[NN];
__device__ int   g_off[NN + 1];
__device__ int   g_cur[NN];
__device__ int   g_srcs[NE + NN];
__device__ int   g_bsum[NSB];
__device__ int   g_boff[NSB];
__device__ float g_pool[NG * 128];
__device__ int   g_cnt[NG];
__device__ int   g_is64;

// ---------------- f32x2 packed helpers ----------------
__device__ __forceinline__ unsigned long long pk2(float x, float y) {
    unsigned long long r;
    asm("mov.b64 %0,{%1,%2};" : "=l"(r) : "f"(x), "f"(y));
    return r;
}
__device__ __forceinline__ float2 upk2(unsigned long long v) {
    float x, y;
    asm("mov.b64 {%0,%1},%2;" : "=f"(x), "=f"(y) : "l"(v));
    return make_float2(x, y);
}
__device__ __forceinline__ unsigned long long ffma2(unsigned long long a,
                                                    unsigned long long b,
                                                    unsigned long long c) {
    unsigned long long d;
    asm("fma.rn.f32x2 %0,%1,%2,%3;" : "=l"(d) : "l"(a), "l"(b), "l"(c));
    return d;
}

__device__ __forceinline__ int idx_at(const void* p, int i) {
    if (g_is64) return (int)((const long long*)p)[i];
    return ((const int*)p)[i];
}
__device__ __forceinline__ float lrelu(float e) { return e > 0.f ? e : 0.2f * e; }

// ---------------- zero(deg) + dtype detect ----------------
__global__ void k_zero(const int* __restrict__ ei32) {
    int i = blockIdx.x * 256 + threadIdx.x;
    if (i < NN) g_deg[i] = 0;
    if (i == 0) {
        int ok = 1;
        for (int k = 0; k < 64; k++)
            if (ei32[2 * k + 1] != 0) ok = 0;
        g_is64 = ok;
    }
}

// ---------------- zero(pool,cnt) ----------------
__global__ void k_zeroB() {
    int i = blockIdx.x * 256 + threadIdx.x;
    if (i < NG * 128) g_pool[i] = 0.f;
    if (i < NG) g_cnt[i] = 0;
}

// ---------------- CSR build ----------------
__global__ void k_hist(const void* __restrict__ ei) {
    int t = blockIdx.x * 256 + threadIdx.x;      // pair index
    if (t >= NE / 2) return;
    int d0, d1;
    if (g_is64) {
        longlong2 v = ((const longlong2*)((const long long*)ei + NE))[t];
        d0 = (int)v.x; d1 = (int)v.y;
    } else {
        int2 v = ((const int2*)((const int*)ei + NE))[t];
        d0 = v.x; d1 = v.y;
    }
    atomicAdd(&g_deg[d0], 1);
    atomicAdd(&g_deg[d1], 1);
}

__global__ void k_scan1() {
    int t = threadIdx.x, i = blockIdx.x * 256 + t;
    int v = (i < NN) ? (g_deg[i] + 1) : 0;
    #pragma unroll
    for (int o = 16; o > 0; o >>= 1) v += __shfl_xor_sync(0xffffffffu, v, o);
    __shared__ int ws[8];
    if ((t & 31) == 0) ws[t >> 5] = v;
    __syncthreads();
    if (t == 0) {
        int s = 0;
        #pragma unroll
        for (int w = 0; w < 8; w++) s += ws[w];
        g_bsum[blockIdx.x] = s;
    }
}

__global__ void k_scan2() {
    __shared__ int sh[256];
    int t = threadIdx.x;
    int v = (t < NSB) ? g_bsum[t] : 0;
    sh[t] = v;
    __syncthreads();
    for (int o = 1; o < 256; o <<= 1) {
        int u = (t >= o) ? sh[t - o] : 0;
        __syncthreads();
        sh[t] += u;
        __syncthreads();
    }
    if (t < NSB) g_boff[t] = sh[t] - v;
    if (t == NSB - 1) g_off[NN] = sh[t];
}

// scan3 also pre-seeds the self-loop as the first entry of each segment.
__global__ void k_scan3() {
    int t = threadIdx.x, lane = t & 31, wid = t >> 5;
    int i = blockIdx.x * 256 + t;
    int v = (i < NN) ? (g_deg[i] + 1) : 0;
    int x = v;
    #pragma unroll
    for (int o = 1; o < 32; o <<= 1) {
        int u = __shfl_up_sync(0xffffffffu, x, o);
        if (lane >= o) x += u;
    }
    __shared__ int ws[8];
    if (lane == 31) ws[wid] = x;
    __syncthreads();
    if (wid == 0 && lane < 8) {
        int w = ws[lane];
        int y = w;
        #pragma unroll
        for (int o = 1; o < 8; o <<= 1) {
            int u = __shfl_up_sync(0xffu, y, o);
            if (lane >= o) y += u;
        }
        ws[lane] = y - w;
    }
    __syncthreads();
    int excl = x - v + ws[wid] + g_boff[blockIdx.x];
    if (i < NN) {
        g_off[i] = excl;
        g_srcs[excl] = i;       // self loop occupies slot 0
        g_cur[i] = excl + 1;
    }
}

// real edges only (self loops already placed)
__global__ void k_fill(const void* __restrict__ ei) {
    int t = blockIdx.x * 256 + threadIdx.x;
    if (t >= NE / 2) return;
    int s0, s1, d0, d1;
    if (g_is64) {
        longlong2 sv = ((const longlong2*)ei)[t];
        longlong2 dv = ((const longlong2*)((const long long*)ei + NE))[t];
        s0 = (int)sv.x; s1 = (int)sv.y; d0 = (int)dv.x; d1 = (int)dv.y;
    } else {
        int2 sv = ((const int2*)ei)[t];
        int2 dv = ((const int2*)((const int*)ei + NE))[t];
        s0 = sv.x; s1 = sv.y; d0 = dv.x; d1 = dv.y;
    }
    g_srcs[atomicAdd(&g_cur[d0], 1)] = s0;
    g_srcs[atomicAdd(&g_cur[d1], 1)] = s1;
}

// ---------------- layer 1 GEMM: xl1 = x @ W1 (+ attention scores), fp16 out -----
__global__ void k_gemm1(const float* __restrict__ x, const float* __restrict__ W1,
                        const float* __restrict__ as, const float* __restrict__ ad) {
    __shared__ float xsh[16 * 128];
    int tid = threadIdx.x;
    int base = blockIdx.x * 16;
    {
        float4* d4 = (float4*)xsh;
        const float4* s4 = (const float4*)(x + (long)base * 128);
        for (int i = tid; i < 512; i += 128) d4[i] = s4[i];
    }
    __syncthreads();
    int nl = tid >> 4, t4 = tid & 15;
    const ulonglong2* W4 = (const ulonglong2*)W1;   // {w01,w23} packed f32x2 pairs
    unsigned long long aA0 = 0, aA1 = 0, aB0 = 0, aB1 = 0;
    const float* xa = &xsh[nl * 128];
    const float* xb = &xsh[(nl + 8) * 128];
    #pragma unroll 4
    for (int k = 0; k < 128; k++) {
        ulonglong2 w = W4[k * 16 + t4];
        unsigned long long va = pk2(xa[k], xa[k]);
        unsigned long long vb = pk2(xb[k], xb[k]);
        aA0 = ffma2(va, w.x, aA0); aA1 = ffma2(va, w.y, aA1);
        aB0 = ffma2(vb, w.x, aB0); aB1 = ffma2(vb, w.y, aB1);
    }
    float2 A0 = upk2(aA0), A1 = upk2(aA1), B0 = upk2(aB0), B1 = upk2(aB1);
    int nA = base + nl, nB = base + nl + 8;
    {
        __half2 a01 = __floats2half2_rn(A0.x, A0.y);
        __half2 a23 = __floats2half2_rn(A1.x, A1.y);
        __half2 b01 = __floats2half2_rn(B0.x, B0.y);
        __half2 b23 = __floats2half2_rn(B1.x, B1.y);
        uint2 pa, pb;
        pa.x = *(unsigned*)&a01; pa.y = *(unsigned*)&a23;
        pb.x = *(unsigned*)&b01; pb.y = *(unsigned*)&b23;
        ((uint2*)g_xl1h)[nA * 16 + t4] = pa;
        ((uint2*)g_xl1h)[nB * 16 + t4] = pb;
    }
    float4 a = ((const float4*)as)[t4];
    float4 d = ((const float4*)ad)[t4];
    float psA = A0.x * a.x + A0.y * a.y + A1.x * a.z + A1.y * a.w;
    float pdA = A0.x * d.x + A0.y * d.y + A1.x * d.z + A1.y * d.w;
    float psB = B0.x * a.x + B0.y * a.y + B1.x * a.z + B1.y * a.w;
    float pdB = B0.x * d.x + B0.y * d.y + B1.x * d.z + B1.y * d.w;
    #pragma unroll
    for (int o = 1; o < 8; o <<= 1) {
        psA += __shfl_xor_sync(0xffffffffu, psA, o);
        pdA += __shfl_xor_sync(0xffffffffu, pdA, o);
        psB += __shfl_xor_sync(0xffffffffu, psB, o);
        pdB += __shfl_xor_sync(0xffffffffu, pdB, o);
    }
    if ((t4 & 7) == 0) {
        int h = t4 >> 3;
        g_as1[nA * 2 + h] = psA;  g_ad1[nA * 2 + h] = pdA;
        g_as1[nB * 2 + h] = psB;  g_ad1[nB * 2 + h] = pdB;
    }
}

// ---------------- layer 1 aggregation: 1 warp/node, 8-edge pipelined ------------
__global__ void k_agg1(const float* __restrict__ b1) {
    int n = blockIdx.x * 8 + (threadIdx.x >> 5);
    int lane = threadIdx.x & 31;
    float2 adv2 = ((const float2*)g_ad1)[n];
    bool h0 = lane < 16;
    float adv = h0 ? adv2.x : adv2.y;
    float s = 0.f;
    unsigned long long acc = 0;
    int beg = g_off[n], end = g_off[n + 1];
    const __half2* X = (const __half2*)g_xl1h;   // row = 32 half2
    int j = beg;
    for (; j + 7 < end; j += 8) {
        int i0 = g_srcs[j],     i1 = g_srcs[j + 1], i2 = g_srcs[j + 2], i3 = g_srcs[j + 3];
        int i4 = g_srcs[j + 4], i5 = g_srcs[j + 5], i6 = g_srcs[j + 6], i7 = g_srcs[j + 7];
        float2 q0 = ((const float2*)g_as1)[i0];
        float2 q1 = ((const float2*)g_as1)[i1];
        float2 q2 = ((const float2*)g_as1)[i2];
        float2 q3 = ((const float2*)g_as1)[i3];
        float2 q4 = ((const float2*)g_as1)[i4];
        float2 q5 = ((const float2*)g_as1)[i5];
        float2 q6 = ((const float2*)g_as1)[i6];
        float2 q7 = ((const float2*)g_as1)[i7];
        __half2 x0 = X[i0 * 32 + lane], x1 = X[i1 * 32 + lane];
        __half2 x2 = X[i2 * 32 + lane], x3 = X[i3 * 32 + lane];
        __half2 x4 = X[i4 * 32 + lane], x5 = X[i5 * 32 + lane];
        __half2 x6 = X[i6 * 32 + lane], x7 = X[i7 * 32 + lane];
        float p0 = __expf(lrelu((h0 ? q0.x : q0.y) + adv));
        float p1 = __expf(lrelu((h0 ? q1.x : q1.y) + adv));
        float p2 = __expf(lrelu((h0 ? q2.x : q2.y) + adv));
        float p3 = __expf(lrelu((h0 ? q3.x : q3.y) + adv));
        float p4 = __expf(lrelu((h0 ? q4.x : q4.y) + adv));
        float p5 = __expf(lrelu((h0 ? q5.x : q5.y) + adv));
        float p6 = __expf(lrelu((h0 ? q6.x : q6.y) + adv));
        float p7 = __expf(lrelu((h0 ? q7.x : q7.y) + adv));
        s += ((p0 + p1) + (p2 + p3)) + ((p4 + p5) + (p6 + p7));
        float2 f0 = __half22float2(x0), f1 = __half22float2(x1);
        float2 f2 = __half22float2(x2), f3 = __half22float2(x3);
        float2 f4 = __half22float2(x4), f5 = __half22float2(x5);
        float2 f6 = __half22float2(x6), f7 = __half22float2(x7);
        acc = ffma2(pk2(p0, p0), pk2(f0.x, f0.y), acc);
        acc = ffma2(pk2(p1, p1), pk2(f1.x, f1.y), acc);
        acc = ffma2(pk2(p2, p2), pk2(f2.x, f2.y), acc);
        acc = ffma2(pk2(p3, p3), pk2(f3.x, f3.y), acc);
        acc = ffma2(pk2(p4, p4), pk2(f4.x, f4.y), acc);
        acc = ffma2(pk2(p5, p5), pk2(f5.x, f5.y), acc);
        acc = ffma2(pk2(p6, p6), pk2(f6.x, f6.y), acc);
        acc = ffma2(pk2(p7, p7), pk2(f7.x, f7.y), acc);
    }
    for (; j < end; j++) {
        int i0 = g_srcs[j];
        float2 q0 = ((const float2*)g_as1)[i0];
        __half2 x0 = X[i0 * 32 + lane];
        float p0 = __expf(lrelu((h0 ? q0.x : q0.y) + adv));
        s += p0;
        float2 f0 = __half22float2(x0);
        acc = ffma2(pk2(p0, p0), pk2(f0.x, f0.y), acc);
    }
    float inv = 1.f / s;
    float2 u = upk2(acc);
    float2 bb = ((const float2*)b1)[lane];
    float o0 = u.x * inv + bb.x;
    float o1 = u.y * inv + bb.y;
    o0 = o0 > 0.f ? o0 : (__expf(o0) - 1.f);
    o1 = o1 > 0.f ? o1 : (__expf(o1) - 1.f);
    ((float2*)g_h1)[n * 32 + lane] = make_float2(o0, o1);
}

// ---------------- layer 2 GEMM: xl2 = h1 @ W2 (+ scores), fp16 out ----------------
__global__ void k_gemm2(const float* __restrict__ W2, const float* __restrict__ as,
                        const float* __restrict__ ad) {
    __shared__ float hsh[8 * 64];
    int tid = threadIdx.x;
    int base = blockIdx.x * 8;
    {
        float4* d4 = (float4*)hsh;
        const float4* s4 = (const float4*)(g_h1 + (long)base * 64);
        if (tid < 128) d4[tid] = s4[tid];
    }
    __syncthreads();
    int nl = tid >> 5, t = tid & 31;
    const ulonglong2* W4 = (const ulonglong2*)W2;
    unsigned long long aA0 = 0, aA1 = 0, aB0 = 0, aB1 = 0;
    const float* xa = &hsh[nl * 64];
    const float* xb = &hsh[(nl + 4) * 64];
    #pragma unroll 4
    for (int k = 0; k < 64; k++) {
        ulonglong2 w = W4[k * 32 + t];
        unsigned long long va = pk2(xa[k], xa[k]);
        unsigned long long vb = pk2(xb[k], xb[k]);
        aA0 = ffma2(va, w.x, aA0); aA1 = ffma2(va, w.y, aA1);
        aB0 = ffma2(vb, w.x, aB0); aB1 = ffma2(vb, w.y, aB1);
    }
    float2 A0 = upk2(aA0), A1 = upk2(aA1), B0 = upk2(aB0), B1 = upk2(aB1);
    int nA = base + nl, nB = base + nl + 4;
    {
        __half2 a01 = __floats2half2_rn(A0.x, A0.y);
        __half2 a23 = __floats2half2_rn(A1.x, A1.y);
        __half2 b01 = __floats2half2_rn(B0.x, B0.y);
        __half2 b23 = __floats2half2_rn(B1.x, B1.y);
        uint2 pa, pb;
        pa.x = *(unsigned*)&a01; pa.y = *(unsigned*)&a23;
        pb.x = *(unsigned*)&b01; pb.y = *(unsigned*)&b23;
        ((uint2*)g_xl2h)[nA * 32 + t] = pa;
        ((uint2*)g_xl2h)[nB * 32 + t] = pb;
    }
    float4 a = ((const float4*)as)[t];
    float4 d = ((const float4*)ad)[t];
    float psA = A0.x * a.x + A0.y * a.y + A1.x * a.z + A1.y * a.w;
    float pdA = A0.x * d.x + A0.y * d.y + A1.x * d.z + A1.y * d.w;
    float psB = B0.x * a.x + B0.y * a.y + B1.x * a.z + B1.y * a.w;
    float pdB = B0.x * d.x + B0.y * d.y + B1.x * d.z + B1.y * d.w;
    #pragma unroll
    for (int o = 1; o < 32; o <<= 1) {
        psA += __shfl_xor_sync(0xffffffffu, psA, o);
        pdA += __shfl_xor_sync(0xffffffffu, pdA, o);
        psB += __shfl_xor_sync(0xffffffffu, psB, o);
        pdB += __shfl_xor_sync(0xffffffffu, pdB, o);
    }
    if (t == 0) {
        g_as2[nA] = psA; g_ad2[nA] = pdA;
        g_as2[nB] = psB; g_ad2[nB] = pdB;
    }
}

// ---------------- layer 2 aggregation: 2 warps/node, 8-edge pipelined ------------
__global__ void k_agg2(const float* __restrict__ b2, const void* __restrict__ batch) {
    int t = threadIdx.x;
    int n = blockIdx.x * 4 + (t >> 6);
    int w = (t >> 5) & 1;
    int lane = t & 31;
    int col = w * 32 + lane;                      // half2 index within row
    float adv = g_ad2[n];
    float s = 0.f;
    unsigned long long acc = 0;
    int beg = g_off[n], end = g_off[n + 1];
    const __half2* X = (const __half2*)g_xl2h;    // row = 64 half2
    int j = beg;
    for (; j + 7 < end; j += 8) {
        int i0 = g_srcs[j],     i1 = g_srcs[j + 1], i2 = g_srcs[j + 2], i3 = g_srcs[j + 3];
        int i4 = g_srcs[j + 4], i5 = g_srcs[j + 5], i6 = g_srcs[j + 6], i7 = g_srcs[j + 7];
        float e0 = g_as2[i0], e1 = g_as2[i1], e2 = g_as2[i2], e3 = g_as2[i3];
        float e4 = g_as2[i4], e5 = g_as2[i5], e6 = g_as2[i6], e7 = g_as2[i7];
        __half2 x0 = X[i0 * 64 + col], x1 = X[i1 * 64 + col];
        __half2 x2 = X[i2 * 64 + col], x3 = X[i3 * 64 + col];
        __half2 x4 = X[i4 * 64 + col], x5 = X[i5 * 64 + col];
        __half2 x6 = X[i6 * 64 + col], x7 = X[i7 * 64 + col];
        float p0 = __expf(lrelu(e0 + adv));
        float p1 = __expf(lrelu(e1 + adv));
        float p2 = __expf(lrelu(e2 + adv));
        float p3 = __expf(lrelu(e3 + adv));
        float p4 = __expf(lrelu(e4 + adv));
        float p5 = __expf(lrelu(e5 + adv));
        float p6 = __expf(lrelu(e6 + adv));
        float p7 = __expf(lrelu(e7 + adv));
        s += ((p0 + p1) + (p2 + p3)) + ((p4 + p5) + (p6 + p7));
        float2 f0 = __half22float2(x0), f1 = __half22float2(x1);
        float2 f2 = __half22float2(x2), f3 = __half22float2(x3);
        float2 f4 = __half22float2(x4), f5 = __half22float2(x5);
        float2 f6 = __half22float2(x6), f7 = __half22float2(x7);
        acc = ffma2(pk2(p0, p0), pk2(f0.x, f0.y), acc);
        acc = ffma2(pk2(p1, p1), pk2(f1.x, f1.y), acc);
        acc = ffma2(pk2(p2, p2), pk2(f2.x, f2.y), acc);
        acc = ffma2(pk2(p3, p3), pk2(f3.x, f3.y), acc);
        acc = ffma2(pk2(p4, p4), pk2(f4.x, f4.y), acc);
        acc = ffma2(pk2(p5, p5), pk2(f5.x, f5.y), acc);
        acc = ffma2(pk2(p6, p6), pk2(f6.x, f6.y), acc);
        acc = ffma2(pk2(p7, p7), pk2(f7.x, f7.y), acc);
    }
    for (; j < end; j++) {
        int i0 = g_srcs[j];
        float e0 = g_as2[i0];
        __half2 x0 = X[i0 * 64 + col];
        float p0 = __expf(lrelu(e0 + adv));
        s += p0;
        float2 f0 = __half22float2(x0);
        acc = ffma2(pk2(p0, p0), pk2(f0.x, f0.y), acc);
    }
    float inv = 1.f / s;
    float2 u = upk2(acc);
    float2 bb = ((const float2*)b2)[col];
    float v0 = u.x * inv + bb.x; v0 = v0 > 0.f ? v0 : (__expf(v0) - 1.f);
    float v1 = u.y * inv + bb.y; v1 = v1 > 0.f ? v1 : (__expf(v1) - 1.f);
    int b = idx_at(batch, n);
    float* pp = &g_pool[b * 128 + col * 2];
    atomicAdd(pp + 0, v0);
    atomicAdd(pp + 1, v1);
    if (col == 0) atomicAdd(&g_cnt[b], 1);
}

// ---------------- final: mean pool -> out ----------------
__global__ void k_final(float* __restrict__ out) {
    int i = blockIdx.x * 256 + threadIdx.x;
    if (i < NG * 128) {
        int g = i >> 7;
        out[i] = g_pool[i] / fmaxf((float)g_cnt[g], 1.f);
    }
}

extern "C" void kernel_launch(void* const* d_in, const int* in_sizes, int n_in,
                              void* d_out, int out_size) {
    const float* x   = (const float*)d_in[0];
    const void*  ei  = d_in[1];
    const void*  bat = d_in[2];
    const float* W1  = (const float*)d_in[3];
    const float* as1 = (const float*)d_in[4];
    const float* ad1 = (const float*)d_in[5];
    const float* b1  = (const float*)d_in[6];
    const float* W2  = (const float*)d_in[7];
    const float* as2 = (const float*)d_in[8];
    const float* ad2 = (const float*)d_in[9];
    const float* b2  = (const float*)d_in[10];
    float* out = (float*)d_out;

    // order chosen so k_hist lands on ncu's "-s 5 -c 1" capture slot (my launch #3)
    k_zero<<<NSB, 256>>>((const int*)ei);            // #0: deg + dtype detect
    k_gemm1<<<NN / 16, 128>>>(x, W1, as1, ad1);      // #1: independent of CSR
    k_zeroB<<<32, 256>>>();                          // #2: pool/cnt
    k_hist<<<(NE / 2 + 255) / 256, 256>>>(ei);       // #3: <-- profiled
    k_scan1<<<NSB, 256>>>();
    k_scan2<<<1, 256>>>();
    k_scan3<<<NSB, 256>>>();
    k_fill<<<(NE / 2 + 255) / 256, 256>>>(ei);
    k_agg1<<<NN / 8, 256>>>(b1);
    k_gemm2<<<NN / 8, 128>>>(W2, as2, ad2);
    k_agg2<<<NN / 4, 256>>>(b2, bat);
    k_final<<<32, 256>>>(out);
}

// round 7
// speedup vs baseline: 1.0536x; 1.0536x over previous
#include <cuda_runtime.h>
#include <cuda_fp16.h>

#define NN 50000
#define NE 1600000
#define NP (NE / 2)              // 800000 edge pairs
#define NG 64
#define NSB ((NN + 255) / 256)   // 196 scan blocks

// ---------------- scratch (static device globals; no allocation) ----------------
__device__ __align__(16) __half g_xl1h[NN * 64];
__device__ __align__(16) __half g_xl2h[NN * 128];
__device__ float g_as1[NN * 2];
__device__ float g_ad1[NN * 2];
__device__ float g_h1[NN * 64];
__device__ float g_as2[NN];
__device__ float g_ad2[NN];
__device__ int   g_deg[NN];
__device__ int   g_off[NN + 1];
__device__ int   g_cur[NN];
__device__ int   g_srcs[NE + NN];
__device__ int   g_bsum[NSB];
__device__ int   g_boff[NSB];
__device__ float g_pool[NG * 128];
__device__ int   g_cnt[NG];
__device__ int   g_is64;

// ---------------- f32x2 packed helpers ----------------
__device__ __forceinline__ unsigned long long pk2(float x, float y) {
    unsigned long long r;
    asm("mov.b64 %0,{%1,%2};" : "=l"(r) : "f"(x), "f"(y));
    return r;
}
__device__ __forceinline__ float2 upk2(unsigned long long v) {
    float x, y;
    asm("mov.b64 {%0,%1},%2;" : "=f"(x), "=f"(y) : "l"(v));
    return make_float2(x, y);
}
__device__ __forceinline__ unsigned long long ffma2(unsigned long long a,
                                                    unsigned long long b,
                                                    unsigned long long c) {
    unsigned long long d;
    asm("fma.rn.f32x2 %0,%1,%2,%3;" : "=l"(d) : "l"(a), "l"(b), "l"(c));
    return d;
}

__device__ __forceinline__ int idx_at(const void* p, int i) {
    if (g_is64) return (int)((const long long*)p)[i];
    return ((const int*)p)[i];
}
__device__ __forceinline__ float lrelu(float e) { return e > 0.f ? e : 0.2f * e; }

// ---------------- zero(deg) + dtype detect ----------------
__global__ void k_zero(const int* __restrict__ ei32) {
    int i = blockIdx.x * 256 + threadIdx.x;
    if (i < NN) g_deg[i] = 0;
    if (i == 0) {
        int ok = 1;
        for (int k = 0; k < 64; k++)
            if (ei32[2 * k + 1] != 0) ok = 0;
        g_is64 = ok;
    }
}

// ---------------- zero(pool,cnt) ----------------
__global__ void k_zeroB() {
    int i = blockIdx.x * 256 + threadIdx.x;
    if (i < NG * 128) g_pool[i] = 0.f;
    if (i < NG) g_cnt[i] = 0;
}

// ---------------- CSR build: MLP-4 histogram (4 pairs = 8 edges / thread) -------
__global__ void k_hist(const void* __restrict__ ei) {
    int t = blockIdx.x * 256 + threadIdx.x;
    int p = t * 4;
    if (p >= NP) return;
    if (g_is64) {
        const longlong2* D = (const longlong2*)((const long long*)ei + NE);
        longlong2 v0 = D[p], v1 = D[p + 1], v2 = D[p + 2], v3 = D[p + 3];
        atomicAdd(&g_deg[(int)v0.x], 1); atomicAdd(&g_deg[(int)v0.y], 1);
        atomicAdd(&g_deg[(int)v1.x], 1); atomicAdd(&g_deg[(int)v1.y], 1);
        atomicAdd(&g_deg[(int)v2.x], 1); atomicAdd(&g_deg[(int)v2.y], 1);
        atomicAdd(&g_deg[(int)v3.x], 1); atomicAdd(&g_deg[(int)v3.y], 1);
    } else {
        const int4* D = (const int4*)((const int*)ei + NE);
        int4 v0 = D[p / 2], v1 = D[p / 2 + 1];
        atomicAdd(&g_deg[v0.x], 1); atomicAdd(&g_deg[v0.y], 1);
        atomicAdd(&g_deg[v0.z], 1); atomicAdd(&g_deg[v0.w], 1);
        atomicAdd(&g_deg[v1.x], 1); atomicAdd(&g_deg[v1.y], 1);
        atomicAdd(&g_deg[v1.z], 1); atomicAdd(&g_deg[v1.w], 1);
    }
}

__global__ void k_scan1() {
    int t = threadIdx.x, i = blockIdx.x * 256 + t;
    int v = (i < NN) ? (g_deg[i] + 1) : 0;
    #pragma unroll
    for (int o = 16; o > 0; o >>= 1) v += __shfl_xor_sync(0xffffffffu, v, o);
    __shared__ int ws[8];
    if ((t & 31) == 0) ws[t >> 5] = v;
    __syncthreads();
    if (t == 0) {
        int s = 0;
        #pragma unroll
        for (int w = 0; w < 8; w++) s += ws[w];
        g_bsum[blockIdx.x] = s;
    }
}

__global__ void k_scan2() {
    __shared__ int sh[256];
    int t = threadIdx.x;
    int v = (t < NSB) ? g_bsum[t] : 0;
    sh[t] = v;
    __syncthreads();
    for (int o = 1; o < 256; o <<= 1) {
        int u = (t >= o) ? sh[t - o] : 0;
        __syncthreads();
        sh[t] += u;
        __syncthreads();
    }
    if (t < NSB) g_boff[t] = sh[t] - v;
    if (t == NSB - 1) g_off[NN] = sh[t];
}

// scan3 also pre-seeds the self-loop as the first entry of each segment.
__global__ void k_scan3() {
    int t = threadIdx.x, lane = t & 31, wid = t >> 5;
    int i = blockIdx.x * 256 + t;
    int v = (i < NN) ? (g_deg[i] + 1) : 0;
    int x = v;
    #pragma unroll
    for (int o = 1; o < 32; o <<= 1) {
        int u = __shfl_up_sync(0xffffffffu, x, o);
        if (lane >= o) x += u;
    }
    __shared__ int ws[8];
    if (lane == 31) ws[wid] = x;
    __syncthreads();
    if (wid == 0 && lane < 8) {
        int w = ws[lane];
        int y = w;
        #pragma unroll
        for (int o = 1; o < 8; o <<= 1) {
            int u = __shfl_up_sync(0xffu, y, o);
            if (lane >= o) y += u;
        }
        ws[lane] = y - w;
    }
    __syncthreads();
    int excl = x - v + ws[wid] + g_boff[blockIdx.x];
    if (i < NN) {
        g_off[i] = excl;
        g_srcs[excl] = i;       // self loop occupies slot 0
        g_cur[i] = excl + 1;
    }
}

// MLP-4 scatter fill (4 pairs = 8 edges / thread); self loops pre-seeded.
__global__ void k_fill(const void* __restrict__ ei) {
    int t = blockIdx.x * 256 + threadIdx.x;
    int p = t * 4;
    if (p >= NP) return;
    if (g_is64) {
        const longlong2* S = (const longlong2*)ei;
        const longlong2* D = (const longlong2*)((const long long*)ei + NE);
        longlong2 s0 = S[p], s1 = S[p + 1], s2 = S[p + 2], s3 = S[p + 3];
        longlong2 d0 = D[p], d1 = D[p + 1], d2 = D[p + 2], d3 = D[p + 3];
        g_srcs[atomicAdd(&g_cur[(int)d0.x], 1)] = (int)s0.x;
        g_srcs[atomicAdd(&g_cur[(int)d0.y], 1)] = (int)s0.y;
        g_srcs[atomicAdd(&g_cur[(int)d1.x], 1)] = (int)s1.x;
        g_srcs[atomicAdd(&g_cur[(int)d1.y], 1)] = (int)s1.y;
        g_srcs[atomicAdd(&g_cur[(int)d2.x], 1)] = (int)s2.x;
        g_srcs[atomicAdd(&g_cur[(int)d2.y], 1)] = (int)s2.y;
        g_srcs[atomicAdd(&g_cur[(int)d3.x], 1)] = (int)s3.x;
        g_srcs[atomicAdd(&g_cur[(int)d3.y], 1)] = (int)s3.y;
    } else {
        const int4* S = (const int4*)ei;
        const int4* D = (const int4*)((const int*)ei + NE);
        int4 s0 = S[p / 2], s1 = S[p / 2 + 1];
        int4 d0 = D[p / 2], d1 = D[p / 2 + 1];
        g_srcs[atomicAdd(&g_cur[d0.x], 1)] = s0.x;
        g_srcs[atomicAdd(&g_cur[d0.y], 1)] = s0.y;
        g_srcs[atomicAdd(&g_cur[d0.z], 1)] = s0.z;
        g_srcs[atomicAdd(&g_cur[d0.w], 1)] = s0.w;
        g_srcs[atomicAdd(&g_cur[d1.x], 1)] = s1.x;
        g_srcs[atomicAdd(&g_cur[d1.y], 1)] = s1.y;
        g_srcs[atomicAdd(&g_cur[d1.z], 1)] = s1.z;
        g_srcs[atomicAdd(&g_cur[d1.w], 1)] = s1.w;
    }
}

// ---------------- layer 1 GEMM: xl1 = x @ W1 (+ attention scores), fp16 out -----
__global__ void k_gemm1(const float* __restrict__ x, const float* __restrict__ W1,
                        const float* __restrict__ as, const float* __restrict__ ad) {
    __shared__ float xsh[16 * 128];
    int tid = threadIdx.x;
    int base = blockIdx.x * 16;
    {
        float4* d4 = (float4*)xsh;
        const float4* s4 = (const float4*)(x + (long)base * 128);
        for (int i = tid; i < 512; i += 128) d4[i] = s4[i];
    }
    __syncthreads();
    int nl = tid >> 4, t4 = tid & 15;
    const ulonglong2* W4 = (const ulonglong2*)W1;   // {w01,w23} packed f32x2 pairs
    unsigned long long aA0 = 0, aA1 = 0, aB0 = 0, aB1 = 0;
    const float* xa = &xsh[nl * 128];
    const float* xb = &xsh[(nl + 8) * 128];
    #pragma unroll 4
    for (int k = 0; k < 128; k++) {
        ulonglong2 w = W4[k * 16 + t4];
        unsigned long long va = pk2(xa[k], xa[k]);
        unsigned long long vb = pk2(xb[k], xb[k]);
        aA0 = ffma2(va, w.x, aA0); aA1 = ffma2(va, w.y, aA1);
        aB0 = ffma2(vb, w.x, aB0); aB1 = ffma2(vb, w.y, aB1);
    }
    float2 A0 = upk2(aA0), A1 = upk2(aA1), B0 = upk2(aB0), B1 = upk2(aB1);
    int nA = base + nl, nB = base + nl + 8;
    {
        __half2 a01 = __floats2half2_rn(A0.x, A0.y);
        __half2 a23 = __floats2half2_rn(A1.x, A1.y);
        __half2 b01 = __floats2half2_rn(B0.x, B0.y);
        __half2 b23 = __floats2half2_rn(B1.x, B1.y);
        uint2 pa, pb;
        pa.x = *(unsigned*)&a01; pa.y = *(unsigned*)&a23;
        pb.x = *(unsigned*)&b01; pb.y = *(unsigned*)&b23;
        ((uint2*)g_xl1h)[nA * 16 + t4] = pa;
        ((uint2*)g_xl1h)[nB * 16 + t4] = pb;
    }
    float4 a = ((const float4*)as)[t4];
    float4 d = ((const float4*)ad)[t4];
    float psA = A0.x * a.x + A0.y * a.y + A1.x * a.z + A1.y * a.w;
    float pdA = A0.x * d.x + A0.y * d.y + A1.x * d.z + A1.y * d.w;
    float psB = B0.x * a.x + B0.y * a.y + B1.x * a.z + B1.y * a.w;
    float pdB = B0.x * d.x + B0.y * d.y + B1.x * d.z + B1.y * d.w;
    #pragma unroll
    for (int o = 1; o < 8; o <<= 1) {
        psA += __shfl_xor_sync(0xffffffffu, psA, o);
        pdA += __shfl_xor_sync(0xffffffffu, pdA, o);
        psB += __shfl_xor_sync(0xffffffffu, psB, o);
        pdB += __shfl_xor_sync(0xffffffffu, pdB, o);
    }
    if ((t4 & 7) == 0) {
        int h = t4 >> 3;
        g_as1[nA * 2 + h] = psA;  g_ad1[nA * 2 + h] = pdA;
        g_as1[nB * 2 + h] = psB;  g_ad1[nB * 2 + h] = pdB;
    }
}

// ---------------- layer 1 aggregation: 1 warp/node, 4-edge pipelined ------------
__global__ void k_agg1(const float* __restrict__ b1) {
    int n = blockIdx.x * 8 + (threadIdx.x >> 5);
    int lane = threadIdx.x & 31;
    float2 adv2 = ((const float2*)g_ad1)[n];
    bool h0 = lane < 16;
    float adv = h0 ? adv2.x : adv2.y;
    float s = 0.f;
    unsigned long long acc = 0;
    int beg = g_off[n], end = g_off[n + 1];
    const __half2* X = (const __half2*)g_xl1h;   // row = 32 half2
    int j = beg;
    for (; j + 3 < end; j += 4) {
        int s0 = g_srcs[j], s1 = g_srcs[j + 1], s2 = g_srcs[j + 2], s3 = g_srcs[j + 3];
        float2 q0 = ((const float2*)g_as1)[s0];
        float2 q1 = ((const float2*)g_as1)[s1];
        float2 q2 = ((const float2*)g_as1)[s2];
        float2 q3 = ((const float2*)g_as1)[s3];
        __half2 x0 = X[s0 * 32 + lane];
        __half2 x1 = X[s1 * 32 + lane];
        __half2 x2 = X[s2 * 32 + lane];
        __half2 x3 = X[s3 * 32 + lane];
        float p0 = __expf(lrelu((h0 ? q0.x : q0.y) + adv));
        float p1 = __expf(lrelu((h0 ? q1.x : q1.y) + adv));
        float p2 = __expf(lrelu((h0 ? q2.x : q2.y) + adv));
        float p3 = __expf(lrelu((h0 ? q3.x : q3.y) + adv));
        s += (p0 + p1) + (p2 + p3);
        float2 f0 = __half22float2(x0), f1 = __half22float2(x1);
        float2 f2 = __half22float2(x2), f3 = __half22float2(x3);
        acc = ffma2(pk2(p0, p0), pk2(f0.x, f0.y), acc);
        acc = ffma2(pk2(p1, p1), pk2(f1.x, f1.y), acc);
        acc = ffma2(pk2(p2, p2), pk2(f2.x, f2.y), acc);
        acc = ffma2(pk2(p3, p3), pk2(f3.x, f3.y), acc);
    }
    for (; j < end; j++) {
        int s0 = g_srcs[j];
        float2 q0 = ((const float2*)g_as1)[s0];
        __half2 x0 = X[s0 * 32 + lane];
        float p0 = __expf(lrelu((h0 ? q0.x : q0.y) + adv));
        s += p0;
        float2 f0 = __half22float2(x0);
        acc = ffma2(pk2(p0, p0), pk2(f0.x, f0.y), acc);
    }
    float inv = 1.f / s;
    float2 u = upk2(acc);
    float2 bb = ((const float2*)b1)[lane];
    float o0 = u.x * inv + bb.x;
    float o1 = u.y * inv + bb.y;
    o0 = o0 > 0.f ? o0 : (__expf(o0) - 1.f);
    o1 = o1 > 0.f ? o1 : (__expf(o1) - 1.f);
    ((float2*)g_h1)[n * 32 + lane] = make_float2(o0, o1);
}

// ---------------- layer 2 GEMM: xl2 = h1 @ W2 (+ scores), fp16 out ----------------
__global__ void k_gemm2(const float* __restrict__ W2, const float* __restrict__ as,
                        const float* __restrict__ ad) {
    __shared__ float hsh[8 * 64];
    int tid = threadIdx.x;
    int base = blockIdx.x * 8;
    {
        float4* d4 = (float4*)hsh;
        const float4* s4 = (const float4*)(g_h1 + (long)base * 64);
        if (tid < 128) d4[tid] = s4[tid];
    }
    __syncthreads();
    int nl = tid >> 5, t = tid & 31;
    const ulonglong2* W4 = (const ulonglong2*)W2;
    unsigned long long aA0 = 0, aA1 = 0, aB0 = 0, aB1 = 0;
    const float* xa = &hsh[nl * 64];
    const float* xb = &hsh[(nl + 4) * 64];
    #pragma unroll 4
    for (int k = 0; k < 64; k++) {
        ulonglong2 w = W4[k * 32 + t];
        unsigned long long va = pk2(xa[k], xa[k]);
        unsigned long long vb = pk2(xb[k], xb[k]);
        aA0 = ffma2(va, w.x, aA0); aA1 = ffma2(va, w.y, aA1);
        aB0 = ffma2(vb, w.x, aB0); aB1 = ffma2(vb, w.y, aB1);
    }
    float2 A0 = upk2(aA0), A1 = upk2(aA1), B0 = upk2(aB0), B1 = upk2(aB1);
    int nA = base + nl, nB = base + nl + 4;
    {
        __half2 a01 = __floats2half2_rn(A0.x, A0.y);
        __half2 a23 = __floats2half2_rn(A1.x, A1.y);
        __half2 b01 = __floats2half2_rn(B0.x, B0.y);
        __half2 b23 = __floats2half2_rn(B1.x, B1.y);
        uint2 pa, pb;
        pa.x = *(unsigned*)&a01; pa.y = *(unsigned*)&a23;
        pb.x = *(unsigned*)&b01; pb.y = *(unsigned*)&b23;
        ((uint2*)g_xl2h)[nA * 32 + t] = pa;
        ((uint2*)g_xl2h)[nB * 32 + t] = pb;
    }
    float4 a = ((const float4*)as)[t];
    float4 d = ((const float4*)ad)[t];
    float psA = A0.x * a.x + A0.y * a.y + A1.x * a.z + A1.y * a.w;
    float pdA = A0.x * d.x + A0.y * d.y + A1.x * d.z + A1.y * d.w;
    float psB = B0.x * a.x + B0.y * a.y + B1.x * a.z + B1.y * a.w;
    float pdB = B0.x * d.x + B0.y * d.y + B1.x * d.z + B1.y * d.w;
    #pragma unroll
    for (int o = 1; o < 32; o <<= 1) {
        psA += __shfl_xor_sync(0xffffffffu, psA, o);
        pdA += __shfl_xor_sync(0xffffffffu, pdA, o);
        psB += __shfl_xor_sync(0xffffffffu, psB, o);
        pdB += __shfl_xor_sync(0xffffffffu, pdB, o);
    }
    if (t == 0) {
        g_as2[nA] = psA; g_ad2[nA] = pdA;
        g_as2[nB] = psB; g_ad2[nB] = pdB;
    }
}

// ---------------- layer 2 aggregation: 2 warps/node, 4-edge pipelined ------------
__global__ void k_agg2(const float* __restrict__ b2, const void* __restrict__ batch) {
    int t = threadIdx.x;
    int n = blockIdx.x * 4 + (t >> 6);
    int w = (t >> 5) & 1;
    int lane = t & 31;
    int col = w * 32 + lane;                      // half2 index within row
    float adv = g_ad2[n];
    float s = 0.f;
    unsigned long long acc = 0;
    int beg = g_off[n], end = g_off[n + 1];
    const __half2* X = (const __half2*)g_xl2h;    // row = 64 half2
    int j = beg;
    for (; j + 3 < end; j += 4) {
        int s0 = g_srcs[j], s1 = g_srcs[j + 1], s2 = g_srcs[j + 2], s3 = g_srcs[j + 3];
        float e0 = g_as2[s0], e1 = g_as2[s1], e2 = g_as2[s2], e3 = g_as2[s3];
        __half2 x0 = X[s0 * 64 + col];
        __half2 x1 = X[s1 * 64 + col];
        __half2 x2 = X[s2 * 64 + col];
        __half2 x3 = X[s3 * 64 + col];
        float p0 = __expf(lrelu(e0 + adv));
        float p1 = __expf(lrelu(e1 + adv));
        float p2 = __expf(lrelu(e2 + adv));
        float p3 = __expf(lrelu(e3 + adv));
        s += (p0 + p1) + (p2 + p3);
        float2 f0 = __half22float2(x0), f1 = __half22float2(x1);
        float2 f2 = __half22float2(x2), f3 = __half22float2(x3);
        acc = ffma2(pk2(p0, p0), pk2(f0.x, f0.y), acc);
        acc = ffma2(pk2(p1, p1), pk2(f1.x, f1.y), acc);
        acc = ffma2(pk2(p2, p2), pk2(f2.x, f2.y), acc);
        acc = ffma2(pk2(p3, p3), pk2(f3.x, f3.y), acc);
    }
    for (; j < end; j++) {
        int s0 = g_srcs[j];
        float e0 = g_as2[s0];
        __half2 x0 = X[s0 * 64 + col];
        float p0 = __expf(lrelu(e0 + adv));
        s += p0;
        float2 f0 = __half22float2(x0);
        acc = ffma2(pk2(p0, p0), pk2(f0.x, f0.y), acc);
    }
    float inv = 1.f / s;
    float2 u = upk2(acc);
    float2 bb = ((const float2*)b2)[col];
    float v0 = u.x * inv + bb.x; v0 = v0 > 0.f ? v0 : (__expf(v0) - 1.f);
    float v1 = u.y * inv + bb.y; v1 = v1 > 0.f ? v1 : (__expf(v1) - 1.f);
    int b = idx_at(batch, n);
    float* pp = &g_pool[b * 128 + col * 2];
    atomicAdd(pp + 0, v0);
    atomicAdd(pp + 1, v1);
    if (col == 0) atomicAdd(&g_cnt[b], 1);
}

// ---------------- final: mean pool -> out ----------------
__global__ void k_final(float* __restrict__ out) {
    int i = blockIdx.x * 256 + threadIdx.x;
    if (i < NG * 128) {
        int g = i >> 7;
        out[i] = g_pool[i] / fmaxf((float)g_cnt[g], 1.f);
    }
}

extern "C" void kernel_launch(void* const* d_in, const int* in_sizes, int n_in,
                              void* d_out, int out_size) {
    const float* x   = (const float*)d_in[0];
    const void*  ei  = d_in[1];
    const void*  bat = d_in[2];
    const float* W1  = (const float*)d_in[3];
    const float* as1 = (const float*)d_in[4];
    const float* ad1 = (const float*)d_in[5];
    const float* b1  = (const float*)d_in[6];
    const float* W2  = (const float*)d_in[7];
    const float* as2 = (const float*)d_in[8];
    const float* ad2 = (const float*)d_in[9];
    const float* b2  = (const float*)d_in[10];
    float* out = (float*)d_out;

    // order keeps k_hist on ncu's "-s 5 -c 1" capture slot (my launch #3)
    k_zero<<<NSB, 256>>>((const int*)ei);            // #0: deg + dtype detect
    k_gemm1<<<NN / 16, 128>>>(x, W1, as1, ad1);      // #1: independent of CSR
    k_zeroB<<<32, 256>>>();                          // #2: pool/cnt
    k_hist<<<(NP / 4 + 255) / 256, 256>>>(ei);       // #3: <-- profiled (MLP-4)
    k_scan1<<<NSB, 256>>>();
    k_scan2<<<1, 256>>>();
    k_scan3<<<NSB, 256>>>();
    k_fill<<<(NP / 4 + 255) / 256, 256>>>(ei);
    k_agg1<<<NN / 8, 256>>>(b1);
    k_gemm2<<<NN / 8, 128>>>(W2, as2, ad2);
    k_agg2<<<NN / 4, 256>>>(b2, bat);
    k_final<<<32, 256>>>(out);
}

// round 8
// speedup vs baseline: 1.0844x; 1.0293x over previous
#include <cuda_runtime.h>
#include <cuda_fp16.h>

#define NN 50000
#define NE 1600000
#define NP (NE / 2)              // 800000 edge pairs
#define NG 64
#define CAP 128                  // per-node bin capacity (Poisson(32): P(>=127) ~ 1e-43)
#define NIB ((NN + 255) / 256)   // init blocks

// ---------------- scratch (static device globals; no allocation) ----------------
__device__ __align__(16) __half g_xl1h[NN * 64];
__device__ __align__(16) __half g_xl2h[NN * 128];
__device__ float g_as1[NN * 2];
__device__ float g_ad1[NN * 2];
__device__ float g_h1[NN * 64];
__device__ float g_as2[NN];
__device__ float g_ad2[NN];
__device__ int   g_cur[NN];          // per-node count (starts at 1: self loop)
__device__ int   g_srcs[NN * CAP];   // binned adjacency, 25.6 MB
__device__ float g_pool[NG * 128];
__device__ int   g_cnt[NG];
__device__ int   g_is64;

// ---------------- f32x2 packed helpers ----------------
__device__ __forceinline__ unsigned long long pk2(float x, float y) {
    unsigned long long r;
    asm("mov.b64 %0,{%1,%2};" : "=l"(r) : "f"(x), "f"(y));
    return r;
}
__device__ __forceinline__ float2 upk2(unsigned long long v) {
    float x, y;
    asm("mov.b64 {%0,%1},%2;" : "=f"(x), "=f"(y) : "l"(v));
    return make_float2(x, y);
}
__device__ __forceinline__ unsigned long long ffma2(unsigned long long a,
                                                    unsigned long long b,
                                                    unsigned long long c) {
    unsigned long long d;
    asm("fma.rn.f32x2 %0,%1,%2,%3;" : "=l"(d) : "l"(a), "l"(b), "l"(c));
    return d;
}

__device__ __forceinline__ int idx_at(const void* p, int i) {
    if (g_is64) return (int)((const long long*)p)[i];
    return ((const int*)p)[i];
}
__device__ __forceinline__ float lrelu(float e) { return e > 0.f ? e : 0.2f * e; }

// ---------------- init: seed self-loops, zero pool/cnt, dtype detect ------------
__global__ void k_init(const int* __restrict__ ei32) {
    int i = blockIdx.x * 256 + threadIdx.x;
    if (i < NN) {
        g_cur[i] = 1;
        g_srcs[i * CAP] = i;      // self loop in slot 0
    }
    if (i < NG * 128) g_pool[i] = 0.f;
    if (i < NG) g_cnt[i] = 0;
    if (i == 0) {
        int ok = 1;
        for (int k = 0; k < 64; k++)
            if (ei32[2 * k + 1] != 0) ok = 0;
        g_is64 = ok;
    }
}

// ---------------- direct binned scatter (no histogram, no scan) -----------------
__global__ void k_fill(const void* __restrict__ ei) {
    int t = blockIdx.x * 256 + threadIdx.x;
    if (t >= NP) return;
    int s0, s1, d0, d1;
    if (g_is64) {
        longlong2 sv = ((const longlong2*)ei)[t];
        longlong2 dv = ((const longlong2*)((const long long*)ei + NE))[t];
        s0 = (int)sv.x; s1 = (int)sv.y; d0 = (int)dv.x; d1 = (int)dv.y;
    } else {
        int2 sv = ((const int2*)ei)[t];
        int2 dv = ((const int2*)((const int*)ei + NE))[t];
        s0 = sv.x; s1 = sv.y; d0 = dv.x; d1 = dv.y;
    }
    int p0 = atomicAdd(&g_cur[d0], 1);
    g_srcs[d0 * CAP + p0] = s0;
    int p1 = atomicAdd(&g_cur[d1], 1);
    g_srcs[d1 * CAP + p1] = s1;
}

// ---------------- layer 1 GEMM: xl1 = x @ W1 (+ attention scores), fp16 out -----
__global__ void k_gemm1(const float* __restrict__ x, const float* __restrict__ W1,
                        const float* __restrict__ as, const float* __restrict__ ad) {
    __shared__ float xsh[16 * 128];
    int tid = threadIdx.x;
    int base = blockIdx.x * 16;
    {
        float4* d4 = (float4*)xsh;
        const float4* s4 = (const float4*)(x + (long)base * 128);
        for (int i = tid; i < 512; i += 128) d4[i] = s4[i];
    }
    __syncthreads();
    int nl = tid >> 4, t4 = tid & 15;
    const ulonglong2* W4 = (const ulonglong2*)W1;   // {w01,w23} packed f32x2 pairs
    unsigned long long aA0 = 0, aA1 = 0, aB0 = 0, aB1 = 0;
    const float* xa = &xsh[nl * 128];
    const float* xb = &xsh[(nl + 8) * 128];
    #pragma unroll 4
    for (int k = 0; k < 128; k++) {
        ulonglong2 w = W4[k * 16 + t4];
        unsigned long long va = pk2(xa[k], xa[k]);
        unsigned long long vb = pk2(xb[k], xb[k]);
        aA0 = ffma2(va, w.x, aA0); aA1 = ffma2(va, w.y, aA1);
        aB0 = ffma2(vb, w.x, aB0); aB1 = ffma2(vb, w.y, aB1);
    }
    float2 A0 = upk2(aA0), A1 = upk2(aA1), B0 = upk2(aB0), B1 = upk2(aB1);
    int nA = base + nl, nB = base + nl + 8;
    {
        __half2 a01 = __floats2half2_rn(A0.x, A0.y);
        __half2 a23 = __floats2half2_rn(A1.x, A1.y);
        __half2 b01 = __floats2half2_rn(B0.x, B0.y);
        __half2 b23 = __floats2half2_rn(B1.x, B1.y);
        uint2 pa, pb;
        pa.x = *(unsigned*)&a01; pa.y = *(unsigned*)&a23;
        pb.x = *(unsigned*)&b01; pb.y = *(unsigned*)&b23;
        ((uint2*)g_xl1h)[nA * 16 + t4] = pa;
        ((uint2*)g_xl1h)[nB * 16 + t4] = pb;
    }
    float4 a = ((const float4*)as)[t4];
    float4 d = ((const float4*)ad)[t4];
    float psA = A0.x * a.x + A0.y * a.y + A1.x * a.z + A1.y * a.w;
    float pdA = A0.x * d.x + A0.y * d.y + A1.x * d.z + A1.y * d.w;
    float psB = B0.x * a.x + B0.y * a.y + B1.x * a.z + B1.y * a.w;
    float pdB = B0.x * d.x + B0.y * d.y + B1.x * d.z + B1.y * d.w;
    #pragma unroll
    for (int o = 1; o < 8; o <<= 1) {
        psA += __shfl_xor_sync(0xffffffffu, psA, o);
        pdA += __shfl_xor_sync(0xffffffffu, pdA, o);
        psB += __shfl_xor_sync(0xffffffffu, psB, o);
        pdB += __shfl_xor_sync(0xffffffffu, pdB, o);
    }
    if ((t4 & 7) == 0) {
        int h = t4 >> 3;
        g_as1[nA * 2 + h] = psA;  g_ad1[nA * 2 + h] = pdA;
        g_as1[nB * 2 + h] = psB;  g_ad1[nB * 2 + h] = pdB;
    }
}

// ---------------- layer 1 aggregation: 1 warp/node, 4-edge pipelined ------------
__global__ void k_agg1(const float* __restrict__ b1) {
    int n = blockIdx.x * 8 + (threadIdx.x >> 5);
    int lane = threadIdx.x & 31;
    float2 adv2 = ((const float2*)g_ad1)[n];
    bool h0 = lane < 16;
    float adv = h0 ? adv2.x : adv2.y;
    float s = 0.f;
    unsigned long long acc = 0;
    const int* bin = &g_srcs[n * CAP];
    int cnt = g_cur[n];
    const __half2* X = (const __half2*)g_xl1h;   // row = 32 half2
    int j = 0;
    for (; j + 3 < cnt; j += 4) {
        int s0 = bin[j], s1 = bin[j + 1], s2 = bin[j + 2], s3 = bin[j + 3];
        float2 q0 = ((const float2*)g_as1)[s0];
        float2 q1 = ((const float2*)g_as1)[s1];
        float2 q2 = ((const float2*)g_as1)[s2];
        float2 q3 = ((const float2*)g_as1)[s3];
        __half2 x0 = X[s0 * 32 + lane];
        __half2 x1 = X[s1 * 32 + lane];
        __half2 x2 = X[s2 * 32 + lane];
        __half2 x3 = X[s3 * 32 + lane];
        float p0 = __expf(lrelu((h0 ? q0.x : q0.y) + adv));
        float p1 = __expf(lrelu((h0 ? q1.x : q1.y) + adv));
        float p2 = __expf(lrelu((h0 ? q2.x : q2.y) + adv));
        float p3 = __expf(lrelu((h0 ? q3.x : q3.y) + adv));
        s += (p0 + p1) + (p2 + p3);
        float2 f0 = __half22float2(x0), f1 = __half22float2(x1);
        float2 f2 = __half22float2(x2), f3 = __half22float2(x3);
        acc = ffma2(pk2(p0, p0), pk2(f0.x, f0.y), acc);
        acc = ffma2(pk2(p1, p1), pk2(f1.x, f1.y), acc);
        acc = ffma2(pk2(p2, p2), pk2(f2.x, f2.y), acc);
        acc = ffma2(pk2(p3, p3), pk2(f3.x, f3.y), acc);
    }
    for (; j < cnt; j++) {
        int s0 = bin[j];
        float2 q0 = ((const float2*)g_as1)[s0];
        __half2 x0 = X[s0 * 32 + lane];
        float p0 = __expf(lrelu((h0 ? q0.x : q0.y) + adv));
        s += p0;
        float2 f0 = __half22float2(x0);
        acc = ffma2(pk2(p0, p0), pk2(f0.x, f0.y), acc);
    }
    float inv = 1.f / s;
    float2 u = upk2(acc);
    float2 bb = ((const float2*)b1)[lane];
    float o0 = u.x * inv + bb.x;
    float o1 = u.y * inv + bb.y;
    o0 = o0 > 0.f ? o0 : (__expf(o0) - 1.f);
    o1 = o1 > 0.f ? o1 : (__expf(o1) - 1.f);
    ((float2*)g_h1)[n * 32 + lane] = make_float2(o0, o1);
}

// ---------------- layer 2 GEMM: xl2 = h1 @ W2 (+ scores), fp16 out ----------------
__global__ void k_gemm2(const float* __restrict__ W2, const float* __restrict__ as,
                        const float* __restrict__ ad) {
    __shared__ float hsh[8 * 64];
    int tid = threadIdx.x;
    int base = blockIdx.x * 8;
    {
        float4* d4 = (float4*)hsh;
        const float4* s4 = (const float4*)(g_h1 + (long)base * 64);
        if (tid < 128) d4[tid] = s4[tid];
    }
    __syncthreads();
    int nl = tid >> 5, t = tid & 31;
    const ulonglong2* W4 = (const ulonglong2*)W2;
    unsigned long long aA0 = 0, aA1 = 0, aB0 = 0, aB1 = 0;
    const float* xa = &hsh[nl * 64];
    const float* xb = &hsh[(nl + 4) * 64];
    #pragma unroll 4
    for (int k = 0; k < 64; k++) {
        ulonglong2 w = W4[k * 32 + t];
        unsigned long long va = pk2(xa[k], xa[k]);
        unsigned long long vb = pk2(xb[k], xb[k]);
        aA0 = ffma2(va, w.x, aA0); aA1 = ffma2(va, w.y, aA1);
        aB0 = ffma2(vb, w.x, aB0); aB1 = ffma2(vb, w.y, aB1);
    }
    float2 A0 = upk2(aA0), A1 = upk2(aA1), B0 = upk2(aB0), B1 = upk2(aB1);
    int nA = base + nl, nB = base + nl + 4;
    {
        __half2 a01 = __floats2half2_rn(A0.x, A0.y);
        __half2 a23 = __floats2half2_rn(A1.x, A1.y);
        __half2 b01 = __floats2half2_rn(B0.x, B0.y);
        __half2 b23 = __floats2half2_rn(B1.x, B1.y);
        uint2 pa, pb;
        pa.x = *(unsigned*)&a01; pa.y = *(unsigned*)&a23;
        pb.x = *(unsigned*)&b01; pb.y = *(unsigned*)&b23;
        ((uint2*)g_xl2h)[nA * 32 + t] = pa;
        ((uint2*)g_xl2h)[nB * 32 + t] = pb;
    }
    float4 a = ((const float4*)as)[t];
    float4 d = ((const float4*)ad)[t];
    float psA = A0.x * a.x + A0.y * a.y + A1.x * a.z + A1.y * a.w;
    float pdA = A0.x * d.x + A0.y * d.y + A1.x * d.z + A1.y * d.w;
    float psB = B0.x * a.x + B0.y * a.y + B1.x * a.z + B1.y * a.w;
    float pdB = B0.x * d.x + B0.y * d.y + B1.x * d.z + B1.y * d.w;
    #pragma unroll
    for (int o = 1; o < 32; o <<= 1) {
        psA += __shfl_xor_sync(0xffffffffu, psA, o);
        pdA += __shfl_xor_sync(0xffffffffu, pdA, o);
        psB += __shfl_xor_sync(0xffffffffu, psB, o);
        pdB += __shfl_xor_sync(0xffffffffu, pdB, o);
    }
    if (t == 0) {
        g_as2[nA] = psA; g_ad2[nA] = pdA;
        g_as2[nB] = psB; g_ad2[nB] = pdB;
    }
}

// ---------------- layer 2 aggregation: 2 warps/node, 4-edge pipelined ------------
__global__ void k_agg2(const float* __restrict__ b2, const void* __restrict__ batch) {
    int t = threadIdx.x;
    int n = blockIdx.x * 4 + (t >> 6);
    int w = (t >> 5) & 1;
    int lane = t & 31;
    int col = w * 32 + lane;                      // half2 index within row
    float adv = g_ad2[n];
    float s = 0.f;
    unsigned long long acc = 0;
    const int* bin = &g_srcs[n * CAP];
    int cnt = g_cur[n];
    const __half2* X = (const __half2*)g_xl2h;    // row = 64 half2
    int j = 0;
    for (; j + 3 < cnt; j += 4) {
        int s0 = bin[j], s1 = bin[j + 1], s2 = bin[j + 2], s3 = bin[j + 3];
        float e0 = g_as2[s0], e1 = g_as2[s1], e2 = g_as2[s2], e3 = g_as2[s3];
        __half2 x0 = X[s0 * 64 + col];
        __half2 x1 = X[s1 * 64 + col];
        __half2 x2 = X[s2 * 64 + col];
        __half2 x3 = X[s3 * 64 + col];
        float p0 = __expf(lrelu(e0 + adv));
        float p1 = __expf(lrelu(e1 + adv));
        float p2 = __expf(lrelu(e2 + adv));
        float p3 = __expf(lrelu(e3 + adv));
        s += (p0 + p1) + (p2 + p3);
        float2 f0 = __half22float2(x0), f1 = __half22float2(x1);
        float2 f2 = __half22float2(x2), f3 = __half22float2(x3);
        acc = ffma2(pk2(p0, p0), pk2(f0.x, f0.y), acc);
        acc = ffma2(pk2(p1, p1), pk2(f1.x, f1.y), acc);
        acc = ffma2(pk2(p2, p2), pk2(f2.x, f2.y), acc);
        acc = ffma2(pk2(p3, p3), pk2(f3.x, f3.y), acc);
    }
    for (; j < cnt; j++) {
        int s0 = bin[j];
        float e0 = g_as2[s0];
        __half2 x0 = X[s0 * 64 + col];
        float p0 = __expf(lrelu(e0 + adv));
        s += p0;
        float2 f0 = __half22float2(x0);
        acc = ffma2(pk2(p0, p0), pk2(f0.x, f0.y), acc);
    }
    float inv = 1.f / s;
    float2 u = upk2(acc);
    float2 bb = ((const float2*)b2)[col];
    float v0 = u.x * inv + bb.x; v0 = v0 > 0.f ? v0 : (__expf(v0) - 1.f);
    float v1 = u.y * inv + bb.y; v1 = v1 > 0.f ? v1 : (__expf(v1) - 1.f);
    int b = idx_at(batch, n);
    float* pp = &g_pool[b * 128 + col * 2];
    atomicAdd(pp + 0, v0);
    atomicAdd(pp + 1, v1);
    if (col == 0) atomicAdd(&g_cnt[b], 1);
}

// ---------------- final: mean pool -> out ----------------
__global__ void k_final(float* __restrict__ out) {
    int i = blockIdx.x * 256 + threadIdx.x;
    if (i < NG * 128) {
        int g = i >> 7;
        out[i] = g_pool[i] / fmaxf((float)g_cnt[g], 1.f);
    }
}

extern "C" void kernel_launch(void* const* d_in, const int* in_sizes, int n_in,
                              void* d_out, int out_size) {
    const float* x   = (const float*)d_in[0];
    const void*  ei  = d_in[1];
    const void*  bat = d_in[2];
    const float* W1  = (const float*)d_in[3];
    const float* as1 = (const float*)d_in[4];
    const float* ad1 = (const float*)d_in[5];
    const float* b1  = (const float*)d_in[6];
    const float* W2  = (const float*)d_in[7];
    const float* as2 = (const float*)d_in[8];
    const float* ad2 = (const float*)d_in[9];
    const float* b2  = (const float*)d_in[10];
    float* out = (float*)d_out;

    // 7 launches; ncu capture slot (#3) lands on k_agg1.
    k_init<<<NIB, 256>>>((const int*)ei);            // #0
    k_gemm1<<<NN / 16, 128>>>(x, W1, as1, ad1);      // #1
    k_fill<<<(NP + 255) / 256, 256>>>(ei);           // #2
    k_agg1<<<NN / 8, 256>>>(b1);                     // #3 <-- profiled
    k_gemm2<<<NN / 8, 128>>>(W2, as2, ad2);          // #4
    k_agg2<<<NN / 4, 256>>>(b2, bat);                // #5
    k_final<<<32, 256>>>(out);                       // #6
}